// round 7
// baseline (speedup 1.0000x reference)
#include <cuda_runtime.h>
#include <cuda_bf16.h>
#include <cstdint>

// 4096-pt FWHT, 8192 rows fp32. One 64-thread CTA per row, grid 8192.
// Radix 64x64: Round A butterflies element bits [11:6] straight out of
// coalesced global loads (f[b] = x[64b + t]); Round B butterflies bits [5:0]
// on contiguous 64-element runs via one skewed smem transpose; a final smem
// pass re-coalesces the output for STG.128.
// Skew: phys(e) = e + (e>>6)*4  -> all four smem patterns bank-conflict-free.
// Packed fma.rn.f32x2 butterflies. ~17KB smem/CTA -> ~12 CTAs/SM; cross-CTA
// phase staggering hides DRAM latency; 1-row CTAs minimize the final-wave tail.

#define ROW   4096
#define TPR   64
#define SROW  4352    // max phys 4347, padded

__device__ __forceinline__ float2 ffma2(float2 b, float2 m, float2 a) {
    float2 r;
    asm("fma.rn.f32x2 %0, %1, %2, %3;"
        : "=l"(reinterpret_cast<unsigned long long&>(r))
        : "l"(reinterpret_cast<const unsigned long long&>(b)),
          "l"(reinterpret_cast<const unsigned long long&>(m)),
          "l"(reinterpret_cast<const unsigned long long&>(a)));
    return r;
}

__device__ __forceinline__ float2 fmul2(float2 a, float2 m) {
    float2 r;
    asm("mul.rn.f32x2 %0, %1, %2;"
        : "=l"(reinterpret_cast<unsigned long long&>(r))
        : "l"(reinterpret_cast<const unsigned long long&>(a)),
          "l"(reinterpret_cast<const unsigned long long&>(m)));
    return r;
}

// 64-pt FWHT over 32 packed float2 (v[p] = (elem 2p, elem 2p+1)).
__device__ __forceinline__ void fwht64p(float2* v) {
    const float2 P1 = make_float2(1.0f, 1.0f);
    const float2 M1 = make_float2(-1.0f, -1.0f);
#pragma unroll
    for (int p = 0; p < 32; p++) {           // h=1 (intra-pair)
        float lo = v[p].x, hi = v[p].y;
        v[p].x = lo + hi;
        v[p].y = lo - hi;
    }
#pragma unroll
    for (int h = 1; h < 32; h <<= 1) {       // h=2..64 packed
#pragma unroll
        for (int p = 0; p < 32; p++) {
            if ((p & h) == 0) {
                float2 a = v[p], b = v[p + h];
                v[p]     = ffma2(b, P1, a);
                v[p + h] = ffma2(b, M1, a);
            }
        }
    }
}

__global__ void __launch_bounds__(TPR)
fwht4096_kernel(const float* __restrict__ in, float* __restrict__ out) {
    __shared__ __align__(16) float s[SROW];

    const int t = threadIdx.x;
    const size_t row_off = (size_t)blockIdx.x * ROW;
    const float* __restrict__ x = in + row_off;
    float* __restrict__       y = out + row_off;

    // ---- Round A: f[b] = x[64b + t]  (coalesced: lanes consecutive, 64 MLP).
    // v[p] = (f[2p], f[2p+1]).
    float2 v[32];
#pragma unroll
    for (int p = 0; p < 32; p++) {
        v[p].x = x[64 * (2 * p)     + t];
        v[p].y = x[64 * (2 * p + 1) + t];
    }
    fwht64p(v);   // butterflies b = element bits [11:6]

    // Apply 1/sqrt(4096) = 1/64 once.
    const float2 SC = make_float2(1.0f / 64.0f, 1.0f / 64.0f);
#pragma unroll
    for (int p = 0; p < 32; p++) v[p] = fmul2(v[p], SC);

    // Scatter: e = 64b + t -> phys = 68b + t. Banks (8p + t) mod 32: clean.
#pragma unroll
    for (int p = 0; p < 32; p++) {
        s[136 * p      + t] = v[p].x;
        s[136 * p + 68 + t] = v[p].y;
    }
    __syncthreads();

    // ---- Round B: thread t owns contiguous e in [64t, 64t+64).
    // phys = 68t + j, j = 0..63 -> 16x LDS.128, banks (4l + 4i): clean.
    float2 w[32];
    {
        const float* base = s + 68 * t;
#pragma unroll
        for (int i = 0; i < 16; i++) {
            float4 q = *reinterpret_cast<const float4*>(base + 4 * i);
            w[2 * i]     = make_float2(q.x, q.y);
            w[2 * i + 1] = make_float2(q.z, q.w);
        }
    }
    fwht64p(w);   // butterflies element bits [5:0]

    // In-place scatter back to the SAME self-owned addresses (no barrier needed).
    {
        float* base = s + 68 * t;
#pragma unroll
        for (int i = 0; i < 16; i++) {
            float4 q;
            q.x = w[2 * i].x;     q.y = w[2 * i].y;
            q.z = w[2 * i + 1].x; q.w = w[2 * i + 1].y;
            *reinterpret_cast<float4*>(base + 4 * i) = q;
        }
    }
    __syncthreads();

    // ---- Coalesced output: float4 q-idx = 64i + t, e = 256i + 4t,
    // phys = 272i + 4t + 4*(t>>4). Banks (16i + 4l + 8w) mod 32: clean.
    {
        const int tskew = 4 * t + 4 * (t >> 4);
        float4* y4 = reinterpret_cast<float4*>(y);
#pragma unroll
        for (int i = 0; i < 16; i++) {
            float4 q = *reinterpret_cast<const float4*>(s + 272 * i + tskew);
            y4[64 * i + t] = q;
        }
    }
}

extern "C" void kernel_launch(void* const* d_in, const int* in_sizes, int n_in,
                              void* d_out, int out_size) {
    const float* x = (const float*)d_in[0];
    float* y = (float*)d_out;
    int total = in_sizes[0];
    int nrows = total / ROW;                 // 8192
    fwht4096_kernel<<<nrows, TPR>>>(x, y);
}

// round 8
// speedup vs baseline: 1.0119x; 1.0119x over previous
#include <cuda_runtime.h>
#include <cuda_bf16.h>
#include <cstdint>

// 4096-pt FWHT, 8192 rows fp32.
// R4-proven pipeline: one 64-thread CTA, 8 rows, double-buffered cp.async.cg
// (stage k+1 -> wait<1> -> barrier -> round A -> barrier -> round B -> STG ->
// trailing barrier). Radix 64x64: Round A butterflies element bits [7:2],
// Round B bits {[11:8],[1:0]}.
// NEW: XOR smem swizzle phys(e) = e ^ (((e>>8)&7)<<2) instead of additive
// skew -> buffer is exactly 4096 words, 32KB/CTA double-buffered ->
// 7 CTAs/SM -> all 1024 CTAs resident in ONE wave (no ragged second wave).
// All smem patterns remain bank-conflict-free. Packed fma.rn.f32x2.

#define ROW    4096
#define TPR    64
#define SROW   4096
#define NCTAS  1024

__device__ __forceinline__ float2 ffma2(float2 b, float2 m, float2 a) {
    float2 r;
    asm("fma.rn.f32x2 %0, %1, %2, %3;"
        : "=l"(reinterpret_cast<unsigned long long&>(r))
        : "l"(reinterpret_cast<const unsigned long long&>(b)),
          "l"(reinterpret_cast<const unsigned long long&>(m)),
          "l"(reinterpret_cast<const unsigned long long&>(a)));
    return r;
}

__device__ __forceinline__ float2 fmul2(float2 a, float2 m) {
    float2 r;
    asm("mul.rn.f32x2 %0, %1, %2;"
        : "=l"(reinterpret_cast<unsigned long long&>(r))
        : "l"(reinterpret_cast<const unsigned long long&>(a)),
          "l"(reinterpret_cast<const unsigned long long&>(m)));
    return r;
}

// 64-pt FWHT over 32 packed float2 (v[p] = (elem 2p, elem 2p+1)).
__device__ __forceinline__ void fwht64p(float2* v) {
    const float2 P1 = make_float2(1.0f, 1.0f);
    const float2 M1 = make_float2(-1.0f, -1.0f);
#pragma unroll
    for (int p = 0; p < 32; p++) {           // h=1 (intra-pair)
        float lo = v[p].x, hi = v[p].y;
        v[p].x = lo + hi;
        v[p].y = lo - hi;
    }
#pragma unroll
    for (int h = 1; h < 32; h <<= 1) {       // h=2..64 packed
#pragma unroll
        for (int p = 0; p < 32; p++) {
            if ((p & h) == 0) {
                float2 a = v[p], b = v[p + h];
                v[p]     = ffma2(b, P1, a);
                v[p + h] = ffma2(b, M1, a);
            }
        }
    }
}

__device__ __forceinline__ void cp_async16(uint32_t dst_smem, const void* src) {
    asm volatile("cp.async.cg.shared.global [%0], [%1], 16;"
                 :: "r"(dst_smem), "l"(src) : "memory");
}
__device__ __forceinline__ void cp_commit() {
    asm volatile("cp.async.commit_group;" ::: "memory");
}
template <int N>
__device__ __forceinline__ void cp_wait() {
    asm volatile("cp.async.wait_group %0;" :: "n"(N) : "memory");
}

// Stage one row: float4 q-idx = i*64 + t (coalesced LDGSTS),
// element e = 256i + 4t -> phys word = 256i + 4*(t ^ (i&7)).
__device__ __forceinline__ void stage_row(uint32_t sbuf, const float4* x4, int t) {
#pragma unroll
    for (int i = 0; i < 16; i++) {
        uint32_t w = 256u * i + 4u * ((uint32_t)t ^ (i & 7));
        cp_async16(sbuf + w * 4u, x4 + i * 64 + t);
    }
    cp_commit();
}

__global__ void __launch_bounds__(TPR)
fwht4096_kernel(const float* __restrict__ in, float* __restrict__ out, int rows_per_cta) {
    __shared__ __align__(16) float s[2 * SROW];

    const int t = threadIdx.x;
    const long row0 = (long)blockIdx.x * rows_per_cta;

    uint32_t sbase;
    asm("{ .reg .u64 tmp; cvta.to.shared.u64 tmp, %1; cvt.u32.u64 %0, tmp; }"
        : "=r"(sbase) : "l"(s));
    const uint32_t sbuf0 = sbase;
    const uint32_t sbuf1 = sbase + SROW * 4u;

    // Prologue: prefetch row 0 into buffer 0.
    stage_row(sbuf0, reinterpret_cast<const float4*>(in + row0 * ROW), t);

    const int j = t >> 2, r = t & 3;       // round-A ownership
    const int jx = j & 7;                   // round-A xor key

    for (int k = 0; k < rows_per_cta; k++) {
        const int cur = k & 1;
        // Prefetch next row into the other buffer (previous iteration's trailing
        // barrier guarantees nobody still reads it).
        if (k + 1 < rows_per_cta) {
            stage_row(cur ? sbuf0 : sbuf1,
                      reinterpret_cast<const float4*>(in + (row0 + k + 1) * ROW), t);
            cp_wait<1>();   // current row's group complete
        } else {
            cp_wait<0>();
        }
        __syncthreads();

        float* sm = s + cur * SROW;

        // ---- Round A: thread (j,r) owns e = j*256 + m*4 + r, m = 0..63.
        // phys = 256j + 4*(m ^ jx) + r; banks 4*((m^j)&7)+r bijective per warp.
        {
            float* base = sm + 256 * j + r;
            float2 v[32];
#pragma unroll
            for (int p = 0; p < 32; p++) {
                v[p].x = base[4 * ((2 * p)     ^ jx)];
                v[p].y = base[4 * ((2 * p + 1) ^ jx)];
            }
            fwht64p(v);   // butterflies bits [7:2]
#pragma unroll
            for (int p = 0; p < 32; p++) {
                base[4 * ((2 * p)     ^ jx)] = v[p].x;
                base[4 * ((2 * p + 1) ^ jx)] = v[p].y;
            }
        }
        __syncthreads();   // round A scatter -> round B gather

        // ---- Round B: thread t owns e = jj*256 + 4t + rr; LDS.128 at
        // phys = 256jj + 4*(t ^ (jj&7)) (xor leaves 16B alignment intact).
        // Butterflies bits {[11:8],[1:0]}, then scaled coalesced STG.128.
        {
            float2 w[32];
#pragma unroll
            for (int jj = 0; jj < 16; jj++) {
                float4 q = *reinterpret_cast<const float4*>(
                    sm + 256 * jj + 4 * (t ^ (jj & 7)));
                w[2 * jj]     = make_float2(q.x, q.y);
                w[2 * jj + 1] = make_float2(q.z, q.w);
            }
            fwht64p(w);

            const float2 SC = make_float2(1.0f / 64.0f, 1.0f / 64.0f);
            float4* y4 = reinterpret_cast<float4*>(out + (row0 + k) * ROW);
#pragma unroll
            for (int jj = 0; jj < 16; jj++) {
                float2 lo = fmul2(w[2 * jj], SC);
                float2 hi = fmul2(w[2 * jj + 1], SC);
                float4 o;
                o.x = lo.x; o.y = lo.y; o.z = hi.x; o.w = hi.y;
                y4[jj * 64 + t] = o;
            }
        }
        // Trailing barrier: protects buf[cur] before next iteration's prefetch.
        __syncthreads();
    }
}

extern "C" void kernel_launch(void* const* d_in, const int* in_sizes, int n_in,
                              void* d_out, int out_size) {
    const float* x = (const float*)d_in[0];
    float* y = (float*)d_out;
    int total = in_sizes[0];
    int nrows = total / ROW;                      // 8192
    int nctas = NCTAS;
    if (nrows % nctas != 0) nctas = nrows;        // fallback: 1 row per CTA
    int rpc = nrows / nctas;
    fwht4096_kernel<<<nctas, TPR>>>(x, y, rpc);
}

// round 9
// speedup vs baseline: 1.1433x; 1.1298x over previous
#include <cuda_runtime.h>
#include <cuda_bf16.h>
#include <cstdint>

// 4096-pt FWHT, 8192 rows fp32.
// R4-proven pipeline: one 64-thread CTA, double-buffered cp.async.cg
// (stage k+1 -> wait<1> -> barrier -> round A -> barrier -> round B -> STG ->
// trailing barrier). Radix 64x64: Round A butterflies element bits [7:2],
// Round B bits {[11:8],[1:0]}. Additive skew phys(e) = e + (e>>8)*4 (folds
// into LDS immediates; all patterns bank-conflict-free). fma.rn.f32x2 math.
// NEW vs R4: rows_per_cta = 2 (grid 4096). 1024 8-row CTAs in 888 resident
// slots gave a 58%-utilization ragged second wave; 4096 2-row CTAs give
// 5-vs-4.61 wave quantization = ~92% schedule efficiency.

#define ROW    4096
#define TPR    64
#define SROW   4160          // skewed row words (max phys 4155, pad to 16B mult)
#define RPC    2
#define NCTAS  4096

__device__ __forceinline__ float2 ffma2(float2 b, float2 m, float2 a) {
    float2 r;
    asm("fma.rn.f32x2 %0, %1, %2, %3;"
        : "=l"(reinterpret_cast<unsigned long long&>(r))
        : "l"(reinterpret_cast<const unsigned long long&>(b)),
          "l"(reinterpret_cast<const unsigned long long&>(m)),
          "l"(reinterpret_cast<const unsigned long long&>(a)));
    return r;
}

__device__ __forceinline__ float2 fmul2(float2 a, float2 m) {
    float2 r;
    asm("mul.rn.f32x2 %0, %1, %2;"
        : "=l"(reinterpret_cast<unsigned long long&>(r))
        : "l"(reinterpret_cast<const unsigned long long&>(a)),
          "l"(reinterpret_cast<const unsigned long long&>(m)));
    return r;
}

// 64-pt FWHT over 32 packed float2 (v[p] = (elem 2p, elem 2p+1)).
__device__ __forceinline__ void fwht64p(float2* v) {
    const float2 P1 = make_float2(1.0f, 1.0f);
    const float2 M1 = make_float2(-1.0f, -1.0f);
#pragma unroll
    for (int p = 0; p < 32; p++) {           // h=1 (intra-pair)
        float lo = v[p].x, hi = v[p].y;
        v[p].x = lo + hi;
        v[p].y = lo - hi;
    }
#pragma unroll
    for (int h = 1; h < 32; h <<= 1) {       // h=2..64 packed
#pragma unroll
        for (int p = 0; p < 32; p++) {
            if ((p & h) == 0) {
                float2 a = v[p], b = v[p + h];
                v[p]     = ffma2(b, P1, a);
                v[p + h] = ffma2(b, M1, a);
            }
        }
    }
}

__device__ __forceinline__ void cp_async16(uint32_t dst_smem, const void* src) {
    asm volatile("cp.async.cg.shared.global [%0], [%1], 16;"
                 :: "r"(dst_smem), "l"(src) : "memory");
}
__device__ __forceinline__ void cp_commit() {
    asm volatile("cp.async.commit_group;" ::: "memory");
}
template <int N>
__device__ __forceinline__ void cp_wait() {
    asm volatile("cp.async.wait_group %0;" :: "n"(N) : "memory");
}

// Stage one row into a smem buffer: float4 q = i*64 + t (coalesced),
// element e = 256*i + 4*t -> skewed word 260*i + 4*t (16B aligned).
__device__ __forceinline__ void stage_row(uint32_t sbuf, const float4* x4, int t) {
#pragma unroll
    for (int i = 0; i < 16; i++)
        cp_async16(sbuf + (260u * i + 4u * t) * 4u, x4 + i * 64 + t);
    cp_commit();
}

__global__ void __launch_bounds__(TPR)
fwht4096_kernel(const float* __restrict__ in, float* __restrict__ out, int rows_per_cta) {
    __shared__ __align__(16) float s[2 * SROW];

    const int t = threadIdx.x;
    const long row0 = (long)blockIdx.x * rows_per_cta;

    uint32_t sbase;
    asm("{ .reg .u64 tmp; cvta.to.shared.u64 tmp, %1; cvt.u32.u64 %0, tmp; }"
        : "=r"(sbase) : "l"(s));
    const uint32_t sbuf0 = sbase;
    const uint32_t sbuf1 = sbase + SROW * 4u;

    // Prologue: prefetch row 0 into buffer 0.
    stage_row(sbuf0, reinterpret_cast<const float4*>(in + row0 * ROW), t);

    const int j = t >> 2, r = t & 3;   // round-A ownership

    for (int k = 0; k < rows_per_cta; k++) {
        const int cur = k & 1;
        // Prefetch next row into the other buffer (previous iteration's trailing
        // barrier guarantees nobody still reads it).
        if (k + 1 < rows_per_cta) {
            stage_row(cur ? sbuf0 : sbuf1,
                      reinterpret_cast<const float4*>(in + (row0 + k + 1) * ROW), t);
            cp_wait<1>();   // current row's group complete
        } else {
            cp_wait<0>();
        }
        __syncthreads();

        float* sm = s + cur * SROW;

        // ---- Round A: thread (j,r) owns e = j*256 + m*4 + r, m = 0..63.
        // Skewed word = 260*j + 4*m + r; banks (4j+r) mod 32 per phase -> clean.
        {
            float* base = sm + 260 * j + r;
            float2 v[32];
#pragma unroll
            for (int p = 0; p < 32; p++)
                v[p] = make_float2(base[8 * p], base[8 * p + 4]);
            fwht64p(v);   // butterflies bits [7:2]
#pragma unroll
            for (int p = 0; p < 32; p++) {
                base[8 * p]     = v[p].x;
                base[8 * p + 4] = v[p].y;
            }
        }
        __syncthreads();   // round A scatter -> round B gather

        // ---- Round B: thread t owns e = jj*256 + 4*t + rr (LDS.128 gather),
        // butterflies bits {[11:8],[1:0]}, then scaled coalesced STG.128.
        {
            float2 w[32];
#pragma unroll
            for (int jj = 0; jj < 16; jj++) {
                float4 q = *reinterpret_cast<const float4*>(sm + 260 * jj + 4 * t);
                w[2 * jj]     = make_float2(q.x, q.y);
                w[2 * jj + 1] = make_float2(q.z, q.w);
            }
            fwht64p(w);

            const float2 SC = make_float2(1.0f / 64.0f, 1.0f / 64.0f);
            float4* y4 = reinterpret_cast<float4*>(out + (row0 + k) * ROW);
#pragma unroll
            for (int jj = 0; jj < 16; jj++) {
                float2 lo = fmul2(w[2 * jj], SC);
                float2 hi = fmul2(w[2 * jj + 1], SC);
                float4 o;
                o.x = lo.x; o.y = lo.y; o.z = hi.x; o.w = hi.y;
                y4[jj * 64 + t] = o;
            }
        }
        // Trailing barrier: protects buf[cur] before next iteration's prefetch.
        __syncthreads();
    }
}

extern "C" void kernel_launch(void* const* d_in, const int* in_sizes, int n_in,
                              void* d_out, int out_size) {
    const float* x = (const float*)d_in[0];
    float* y = (float*)d_out;
    int total = in_sizes[0];
    int nrows = total / ROW;                      // 8192
    int nctas = nrows / RPC;                      // 4096
    int rpc = RPC;
    if (nrows % RPC != 0) { nctas = nrows; rpc = 1; }
    fwht4096_kernel<<<nctas, TPR>>>(x, y, rpc);
}